// round 11
// baseline (speedup 1.0000x reference)
#include <cuda_runtime.h>
#include <cstdint>

#define NXG    512
#define NYG    512
#define NCELL  (NXG * NYG)   // 262144
#define MAXB   8             // scratch sized for up to 8 batches
#define CELLS_PER_BLOCK 512

// Inverse map cell -> (global pillar index + 1), 0 = empty.
// INVARIANT: all-zero at the start of every kernel_launch call:
//   - zero-initialized at module load
//   - bev_write zeroes every cell it reads at the end of each call
// Therefore any nonzero entry seen by bev_write was written by THIS call's
// build_inv and is valid by construction -> no validation needed.
__device__ unsigned short g_inv16[MAXB * NCELL];
__device__ int            g_inv32[MAXB * NCELL];

// ---------------------------------------------------------------------------
template <typename T>
__global__ void build_inv_kernel(const int* __restrict__ coords,
                                 const int* __restrict__ mask,
                                 T* __restrict__ inv,
                                 int BP, int P)
{
    int bp = blockIdx.x * blockDim.x + threadIdx.x;
    if (bp < BP && mask[bp] > 0) {
        int2 cc = ((const int2*)coords)[bp];
        int b  = bp / P;
        inv[b * NCELL + cc.y * NXG + cc.x] = (T)(bp + 1);
    }
#if __CUDA_ARCH__ >= 900
    cudaTriggerProgrammaticLaunchCompletion();
#endif
}

// ---------------------------------------------------------------------------
// Kernel C: block owns CELLS_PER_BLOCK consecutive cells of batch blockIdx.y
// across ALL channels. Warp w writes channel slice [w*CPW, (w+1)*CPW).
// After all warps finish reading inv, the block zeroes its inv slice.
// Launched with PDL: waits on build_inv only at the inv read.
template <typename T, int CPW>   // CPW = channels per warp (C / 8)
__global__ void __launch_bounds__(256)
bev_write_kernel(const float* __restrict__ emb,
                 const T*     __restrict__ inv,
                 float*       __restrict__ out,
                 int C)
{
    int b     = blockIdx.y;
    int cell0 = blockIdx.x * CELLS_PER_BLOCK;
    int warp  = threadIdx.x >> 5;
    int lane  = threadIdx.x & 31;
    int c0    = warp * CPW;

#if __CUDA_ARCH__ >= 900
    cudaGridDependencySynchronize();   // build_inv results must be visible
#endif

    const T* invb  = inv + b * NCELL + cell0;
    float*   outb  = out + ((long long)b * C + c0) * NCELL + cell0;

    #pragma unroll
    for (int q = 0; q < CELLS_PER_BLOCK / 128; q++) {     // 4 quads per lane
        int quad = q * 32 + lane;          // quad index within block
        int cell = quad * 4;

        int v0, v1, v2, v3;
        if (sizeof(T) == 2) {
            const ushort4 pi = *(const ushort4*)(&invb[cell]);
            v0 = pi.x; v1 = pi.y; v2 = pi.z; v3 = pi.w;
        } else {
            const int4 pi = *(const int4*)(&invb[cell]);
            v0 = pi.x; v1 = pi.y; v2 = pi.z; v3 = pi.w;
        }

        const float* e0 = v0 ? emb + (long long)(v0 - 1) * C + c0 : nullptr;
        const float* e1 = v1 ? emb + (long long)(v1 - 1) * C + c0 : nullptr;
        const float* e2 = v2 ? emb + (long long)(v2 - 1) * C + c0 : nullptr;
        const float* e3 = v3 ? emb + (long long)(v3 - 1) * C + c0 : nullptr;

        #pragma unroll
        for (int c = 0; c < CPW; c++) {
            float4 v;
            v.x = e0 ? e0[c] : 0.0f;
            v.y = e1 ? e1[c] : 0.0f;
            v.z = e2 ? e2[c] : 0.0f;
            v.w = e3 ? e3[c] : 0.0f;
            __stcs((float4*)(outb + (long long)c * NCELL + cell), v);
        }
    }

    // restore the all-zero invariant for the next call
    __syncthreads();
    const int nclr = CELLS_PER_BLOCK * (int)sizeof(T) / 16;   // int4 stores
    if (threadIdx.x < nclr)
        ((int4*)invb)[threadIdx.x] = make_int4(0, 0, 0, 0);
}

// ---------------------------------------------------------------------------
template <typename T, int CPW>
static void launch_bev(const float* emb, T* inv, float* out, int C, int B)
{
    cudaLaunchAttribute attr[1];
    attr[0].id = cudaLaunchAttributeProgrammaticStreamSerialization;
    attr[0].val.programmaticStreamSerializationAllowed = 1;

    cudaLaunchConfig_t cfg = {};
    cfg.gridDim  = dim3(NCELL / CELLS_PER_BLOCK, B, 1);
    cfg.blockDim = dim3(256, 1, 1);
    cfg.dynamicSmemBytes = 0;
    cfg.stream   = 0;
    cfg.attrs    = attr;
    cfg.numAttrs = 1;

    cudaError_t err = cudaLaunchKernelEx(&cfg, bev_write_kernel<T, CPW>,
                                         emb, (const T*)inv, out, C);
    if (err != cudaSuccess) {
        bev_write_kernel<T, CPW><<<cfg.gridDim, cfg.blockDim>>>(
            emb, (const T*)inv, out, C);
    }
}

template <typename T>
static void launch_path(const float* emb, const int* coords, const int* mask,
                        T* inv, float* out, int BP, int P, int C, int B)
{
    int threads = 256;
    int bblocks = (BP + threads - 1) / threads;
    build_inv_kernel<T><<<bblocks, threads>>>(coords, mask, inv, BP, P);

    switch (C) {
        case 64:  launch_bev<T, 8>(emb, inv, out, C, B); break;   // actual shape
        case 128: launch_bev<T, 16>(emb, inv, out, C, B); break;
        case 32:  launch_bev<T, 4>(emb, inv, out, C, B); break;
        default:  launch_bev<T, 8>(emb, inv, out, C, B); break;   // C must be 64-like
    }
}

extern "C" void kernel_launch(void* const* d_in, const int* in_sizes, int n_in,
                              void* d_out, int out_size)
{
    const float* emb    = (const float*)d_in[0];   // [B, P, C] f32
    const int*   coords = (const int*)  d_in[1];   // [B, P, 2] i32
    const int*   mask   = (const int*)  d_in[2];   // [B, P]    i32

    int BP = in_sizes[2];                 // B*P
    int C  = in_sizes[0] / BP;            // 64
    int B  = out_size / (C * NCELL);      // 4
    int P  = BP / B;

    float* out = (float*)d_out;

    if (BP + 1 <= 65535) {
        unsigned short* inv = nullptr;
        cudaGetSymbolAddress((void**)&inv, g_inv16);
        launch_path<unsigned short>(emb, coords, mask, inv, out, BP, P, C, B);
    } else {
        int* inv = nullptr;
        cudaGetSymbolAddress((void**)&inv, g_inv32);
        launch_path<int>(emb, coords, mask, inv, out, BP, P, C, B);
    }
}

// round 12
// speedup vs baseline: 1.0517x; 1.0517x over previous
#include <cuda_runtime.h>
#include <cstdint>

#define NXG    512
#define NYG    512
#define NCELL  (NXG * NYG)   // 262144
#define MAXB   8             // scratch sized for up to 8 batches
#define CCHUNK 8             // channels per block (R8-proven best wall-clock)
#define MAXBP16 65536

// Inverse map cell -> (global pillar index + 1), 0 = empty. Never zeroed at
// runtime; entries are validated against the fresh key table below.
__device__ unsigned short g_inv16[MAXB * NCELL];
__device__ int            g_inv32[MAXB * NCELL];
// key[bp] = global inv index (b*NCELL + cell) of pillar bp if valid, else -1.
// Fully overwritten for all bp < BP on every call -> never stale.
__device__ int            g_key[MAXBP16];

// ---------------------------------------------------------------------------
// u16 path: writes inv for valid pillars AND key for every bp < BP.
__global__ void build_inv16_kernel(const int* __restrict__ coords,
                                   const int* __restrict__ mask,
                                   unsigned short* __restrict__ inv,
                                   int BP, int P)
{
    int bp = blockIdx.x * blockDim.x + threadIdx.x;
    if (bp < BP) {
        int k = -1;
        if (mask[bp] > 0) {
            int2 cc = ((const int2*)coords)[bp];
            int b = bp / P;
            int gidx = b * NCELL + cc.y * NXG + cc.x;
            inv[gidx] = (unsigned short)(bp + 1);
            k = gidx;
        }
        g_key[bp] = k;
    }
#if __CUDA_ARCH__ >= 900
    cudaTriggerProgrammaticLaunchCompletion();
#endif
}

// int32 fallback (BP too large for u16): full input validation, R8-style.
__global__ void build_inv32_kernel(const int* __restrict__ coords,
                                   const int* __restrict__ mask,
                                   int* __restrict__ inv,
                                   int BP, int P)
{
    int bp = blockIdx.x * blockDim.x + threadIdx.x;
    if (bp < BP && mask[bp] > 0) {
        int2 cc = ((const int2*)coords)[bp];
        int b = bp / P;
        inv[b * NCELL + cc.y * NXG + cc.x] = bp + 1;
    }
#if __CUDA_ARCH__ >= 900
    cudaTriggerProgrammaticLaunchCompletion();
#endif
}

// ---------------------------------------------------------------------------
// Fast validation: one L2-hit load + compare. key is fresh every call.
__device__ __forceinline__
const float* validate16(int v, int gidx, int BP,
                        const float* __restrict__ emb, int cs, int c0)
{
    if (v == 0) return nullptr;
    int bp = v - 1;
    if (bp >= BP) return nullptr;              // key beyond BP is untrusted
    if (g_key[bp] != gidx) return nullptr;     // stale inv entry
    return emb + (long long)bp * cs + c0;
}

// Full validation for the int32 fallback path.
__device__ __forceinline__
const float* validate32(int v, int gidx, int b,
                        const float* __restrict__ emb,
                        const int*   __restrict__ coords,
                        const int*   __restrict__ mask,
                        int BP, int P, int cs, int c0)
{
    if (v == 0) return nullptr;
    int bp = v - 1;
    if (bp >= BP) return nullptr;
    if (bp / P != b) return nullptr;
    if (mask[bp] <= 0) return nullptr;
    int2 cc = ((const int2*)coords)[bp];
    if ((b * NCELL + cc.y * NXG + cc.x) != gidx) return nullptr;
    return emb + (long long)bp * cs + c0;
}

// ---------------------------------------------------------------------------
// Kernel C (u16): R8 shape — grid (NCELL/1024, C/CCHUNK, B), 4 cells/thread,
// CCHUNK channel planes, float4 streaming stores, PDL on build_inv.
template <int CT>
__global__ void __launch_bounds__(256)
bev_write16_kernel(const float* __restrict__ emb,
                   const unsigned short* __restrict__ inv,
                   float* __restrict__ out,
                   int BP, int C)
{
    const int cs = (CT > 0) ? CT : C;
    int b        = blockIdx.z;
    int c0       = blockIdx.y * CCHUNK;
    int cellBase = (blockIdx.x * 256 + threadIdx.x) * 4;
    int gidx     = b * NCELL + cellBase;

    float* obase = out + ((long long)b * cs + c0) * NCELL + cellBase;

#if __CUDA_ARCH__ >= 900
    cudaGridDependencySynchronize();   // inv + key must be visible
#endif

    const ushort4 pi = *(const ushort4*)(&inv[gidx]);

    const float* e0 = validate16(pi.x, gidx + 0, BP, emb, cs, c0);
    const float* e1 = validate16(pi.y, gidx + 1, BP, emb, cs, c0);
    const float* e2 = validate16(pi.z, gidx + 2, BP, emb, cs, c0);
    const float* e3 = validate16(pi.w, gidx + 3, BP, emb, cs, c0);

    #pragma unroll
    for (int c = 0; c < CCHUNK; c++) {
        float4 v;
        v.x = e0 ? e0[c] : 0.0f;
        v.y = e1 ? e1[c] : 0.0f;
        v.z = e2 ? e2[c] : 0.0f;
        v.w = e3 ? e3[c] : 0.0f;
        __stcs((float4*)(obase + (long long)c * NCELL), v);
    }
}

// Kernel C (int32 fallback): full validation.
__global__ void __launch_bounds__(256)
bev_write32_kernel(const float* __restrict__ emb,
                   const int* __restrict__ coords,
                   const int* __restrict__ mask,
                   const int* __restrict__ inv,
                   float* __restrict__ out,
                   int BP, int P, int C)
{
    int b        = blockIdx.z;
    int c0       = blockIdx.y * CCHUNK;
    int cellBase = (blockIdx.x * 256 + threadIdx.x) * 4;
    int gidx     = b * NCELL + cellBase;

    float* obase = out + ((long long)b * C + c0) * NCELL + cellBase;

#if __CUDA_ARCH__ >= 900
    cudaGridDependencySynchronize();
#endif

    const int4 pi = *(const int4*)(&inv[gidx]);

    const float* e0 = validate32(pi.x, gidx + 0, b, emb, coords, mask, BP, P, C, c0);
    const float* e1 = validate32(pi.y, gidx + 1, b, emb, coords, mask, BP, P, C, c0);
    const float* e2 = validate32(pi.z, gidx + 2, b, emb, coords, mask, BP, P, C, c0);
    const float* e3 = validate32(pi.w, gidx + 3, b, emb, coords, mask, BP, P, C, c0);

    #pragma unroll
    for (int c = 0; c < CCHUNK; c++) {
        float4 v;
        v.x = e0 ? e0[c] : 0.0f;
        v.y = e1 ? e1[c] : 0.0f;
        v.z = e2 ? e2[c] : 0.0f;
        v.w = e3 ? e3[c] : 0.0f;
        __stcs((float4*)(obase + (long long)c * NCELL), v);
    }
}

// ---------------------------------------------------------------------------
template <typename F, typename... Args>
static void launch_pdl(dim3 grid, F* func, Args... args)
{
    cudaLaunchAttribute attr[1];
    attr[0].id = cudaLaunchAttributeProgrammaticStreamSerialization;
    attr[0].val.programmaticStreamSerializationAllowed = 1;

    cudaLaunchConfig_t cfg = {};
    cfg.gridDim  = grid;
    cfg.blockDim = dim3(256, 1, 1);
    cfg.dynamicSmemBytes = 0;
    cfg.stream   = 0;
    cfg.attrs    = attr;
    cfg.numAttrs = 1;

    if (cudaLaunchKernelEx(&cfg, func, args...) != cudaSuccess)
        func<<<grid, 256>>>(args...);
}

extern "C" void kernel_launch(void* const* d_in, const int* in_sizes, int n_in,
                              void* d_out, int out_size)
{
    const float* emb    = (const float*)d_in[0];   // [B, P, C] f32
    const int*   coords = (const int*)  d_in[1];   // [B, P, 2] i32
    const int*   mask   = (const int*)  d_in[2];   // [B, P]    i32

    int BP = in_sizes[2];                 // B*P
    int C  = in_sizes[0] / BP;            // 64
    int B  = out_size / (C * NCELL);      // 4
    int P  = BP / B;

    float* out = (float*)d_out;

    int threads = 256;
    int bblocks = (BP + threads - 1) / threads;
    dim3 cgrid(NCELL / 1024, C / CCHUNK, B);

    if (BP + 1 <= 65535) {
        unsigned short* inv = nullptr;
        cudaGetSymbolAddress((void**)&inv, g_inv16);
        build_inv16_kernel<<<bblocks, threads>>>(coords, mask, inv, BP, P);
        if (C == 64)
            launch_pdl(cgrid, bev_write16_kernel<64>, emb,
                       (const unsigned short*)inv, out, BP, C);
        else
            launch_pdl(cgrid, bev_write16_kernel<0>, emb,
                       (const unsigned short*)inv, out, BP, C);
    } else {
        int* inv = nullptr;
        cudaGetSymbolAddress((void**)&inv, g_inv32);
        build_inv32_kernel<<<bblocks, threads>>>(coords, mask, inv, BP, P);
        launch_pdl(cgrid, bev_write32_kernel, emb, coords, mask,
                   (const int*)inv, out, BP, P, C);
    }
}

// round 13
// speedup vs baseline: 1.0596x; 1.0074x over previous
#include <cuda_runtime.h>
#include <cstdint>

#define NXG    512
#define NYG    512
#define NCELL  (NXG * NYG)   // 262144
#define MAXB   8             // scratch sized for up to 8 batches
#define CCHUNK 4             // channels per block (bisect: 16->45.1, 8->43.1, 4->?)
#define MAXBP16 65536

// Inverse map cell -> (global pillar index + 1), 0 = empty. Never zeroed at
// runtime; entries are validated against the fresh key table below.
__device__ unsigned short g_inv16[MAXB * NCELL];
__device__ int            g_inv32[MAXB * NCELL];
// key[bp] = global inv index (b*NCELL + cell) of pillar bp if valid, else -1.
// Fully overwritten for all bp < BP on every call -> never stale.
__device__ int            g_key[MAXBP16];

// ---------------------------------------------------------------------------
// u16 path: writes inv for valid pillars AND key for every bp < BP.
__global__ void build_inv16_kernel(const int* __restrict__ coords,
                                   const int* __restrict__ mask,
                                   unsigned short* __restrict__ inv,
                                   int BP, int P)
{
    int bp = blockIdx.x * blockDim.x + threadIdx.x;
    if (bp < BP) {
        int k = -1;
        if (mask[bp] > 0) {
            int2 cc = ((const int2*)coords)[bp];
            int b = bp / P;
            int gidx = b * NCELL + cc.y * NXG + cc.x;
            inv[gidx] = (unsigned short)(bp + 1);
            k = gidx;
        }
        g_key[bp] = k;
    }
#if __CUDA_ARCH__ >= 900
    cudaTriggerProgrammaticLaunchCompletion();
#endif
}

// int32 fallback (BP too large for u16): full input validation.
__global__ void build_inv32_kernel(const int* __restrict__ coords,
                                   const int* __restrict__ mask,
                                   int* __restrict__ inv,
                                   int BP, int P)
{
    int bp = blockIdx.x * blockDim.x + threadIdx.x;
    if (bp < BP && mask[bp] > 0) {
        int2 cc = ((const int2*)coords)[bp];
        int b = bp / P;
        inv[b * NCELL + cc.y * NXG + cc.x] = bp + 1;
    }
#if __CUDA_ARCH__ >= 900
    cudaTriggerProgrammaticLaunchCompletion();
#endif
}

// ---------------------------------------------------------------------------
// Fast validation: one L2-hit load + compare. key is fresh every call.
__device__ __forceinline__
const float* validate16(int v, int gidx, int BP,
                        const float* __restrict__ emb, int cs, int c0)
{
    if (v == 0) return nullptr;
    int bp = v - 1;
    if (bp >= BP) return nullptr;              // key beyond BP is untrusted
    if (g_key[bp] != gidx) return nullptr;     // stale inv entry
    return emb + (long long)bp * cs + c0;
}

// Full validation for the int32 fallback path.
__device__ __forceinline__
const float* validate32(int v, int gidx, int b,
                        const float* __restrict__ emb,
                        const int*   __restrict__ coords,
                        const int*   __restrict__ mask,
                        int BP, int P, int cs, int c0)
{
    if (v == 0) return nullptr;
    int bp = v - 1;
    if (bp >= BP) return nullptr;
    if (bp / P != b) return nullptr;
    if (mask[bp] <= 0) return nullptr;
    int2 cc = ((const int2*)coords)[bp];
    if ((b * NCELL + cc.y * NXG + cc.x) != gidx) return nullptr;
    return emb + (long long)bp * cs + c0;
}

// ---------------------------------------------------------------------------
// Kernel C (u16): grid (NCELL/1024, C/CCHUNK, B), 4 cells/thread,
// CCHUNK channel planes, float4 streaming stores, PDL on build_inv.
template <int CT>
__global__ void __launch_bounds__(256)
bev_write16_kernel(const float* __restrict__ emb,
                   const unsigned short* __restrict__ inv,
                   float* __restrict__ out,
                   int BP, int C)
{
    const int cs = (CT > 0) ? CT : C;
    int b        = blockIdx.z;
    int c0       = blockIdx.y * CCHUNK;
    int cellBase = (blockIdx.x * 256 + threadIdx.x) * 4;
    int gidx     = b * NCELL + cellBase;

    float* obase = out + ((long long)b * cs + c0) * NCELL + cellBase;

#if __CUDA_ARCH__ >= 900
    cudaGridDependencySynchronize();   // inv + key must be visible
#endif

    const ushort4 pi = *(const ushort4*)(&inv[gidx]);

    const float* e0 = validate16(pi.x, gidx + 0, BP, emb, cs, c0);
    const float* e1 = validate16(pi.y, gidx + 1, BP, emb, cs, c0);
    const float* e2 = validate16(pi.z, gidx + 2, BP, emb, cs, c0);
    const float* e3 = validate16(pi.w, gidx + 3, BP, emb, cs, c0);

    #pragma unroll
    for (int c = 0; c < CCHUNK; c++) {
        float4 v;
        v.x = e0 ? e0[c] : 0.0f;
        v.y = e1 ? e1[c] : 0.0f;
        v.z = e2 ? e2[c] : 0.0f;
        v.w = e3 ? e3[c] : 0.0f;
        __stcs((float4*)(obase + (long long)c * NCELL), v);
    }
}

// Kernel C (int32 fallback): full validation.
__global__ void __launch_bounds__(256)
bev_write32_kernel(const float* __restrict__ emb,
                   const int* __restrict__ coords,
                   const int* __restrict__ mask,
                   const int* __restrict__ inv,
                   float* __restrict__ out,
                   int BP, int P, int C)
{
    int b        = blockIdx.z;
    int c0       = blockIdx.y * CCHUNK;
    int cellBase = (blockIdx.x * 256 + threadIdx.x) * 4;
    int gidx     = b * NCELL + cellBase;

    float* obase = out + ((long long)b * C + c0) * NCELL + cellBase;

#if __CUDA_ARCH__ >= 900
    cudaGridDependencySynchronize();
#endif

    const int4 pi = *(const int4*)(&inv[gidx]);

    const float* e0 = validate32(pi.x, gidx + 0, b, emb, coords, mask, BP, P, C, c0);
    const float* e1 = validate32(pi.y, gidx + 1, b, emb, coords, mask, BP, P, C, c0);
    const float* e2 = validate32(pi.z, gidx + 2, b, emb, coords, mask, BP, P, C, c0);
    const float* e3 = validate32(pi.w, gidx + 3, b, emb, coords, mask, BP, P, C, c0);

    #pragma unroll
    for (int c = 0; c < CCHUNK; c++) {
        float4 v;
        v.x = e0 ? e0[c] : 0.0f;
        v.y = e1 ? e1[c] : 0.0f;
        v.z = e2 ? e2[c] : 0.0f;
        v.w = e3 ? e3[c] : 0.0f;
        __stcs((float4*)(obase + (long long)c * NCELL), v);
    }
}

// ---------------------------------------------------------------------------
template <typename F, typename... Args>
static void launch_pdl(dim3 grid, F* func, Args... args)
{
    cudaLaunchAttribute attr[1];
    attr[0].id = cudaLaunchAttributeProgrammaticStreamSerialization;
    attr[0].val.programmaticStreamSerializationAllowed = 1;

    cudaLaunchConfig_t cfg = {};
    cfg.gridDim  = grid;
    cfg.blockDim = dim3(256, 1, 1);
    cfg.dynamicSmemBytes = 0;
    cfg.stream   = 0;
    cfg.attrs    = attr;
    cfg.numAttrs = 1;

    if (cudaLaunchKernelEx(&cfg, func, args...) != cudaSuccess)
        func<<<grid, 256>>>(args...);
}

extern "C" void kernel_launch(void* const* d_in, const int* in_sizes, int n_in,
                              void* d_out, int out_size)
{
    const float* emb    = (const float*)d_in[0];   // [B, P, C] f32
    const int*   coords = (const int*)  d_in[1];   // [B, P, 2] i32
    const int*   mask   = (const int*)  d_in[2];   // [B, P]    i32

    int BP = in_sizes[2];                 // B*P
    int C  = in_sizes[0] / BP;            // 64
    int B  = out_size / (C * NCELL);      // 4
    int P  = BP / B;

    float* out = (float*)d_out;

    int threads = 256;
    int bblocks = (BP + threads - 1) / threads;
    dim3 cgrid(NCELL / 1024, C / CCHUNK, B);

    if (BP + 1 <= 65535) {
        unsigned short* inv = nullptr;
        cudaGetSymbolAddress((void**)&inv, g_inv16);
        build_inv16_kernel<<<bblocks, threads>>>(coords, mask, inv, BP, P);
        if (C == 64)
            launch_pdl(cgrid, bev_write16_kernel<64>, emb,
                       (const unsigned short*)inv, out, BP, C);
        else
            launch_pdl(cgrid, bev_write16_kernel<0>, emb,
                       (const unsigned short*)inv, out, BP, C);
    } else {
        int* inv = nullptr;
        cudaGetSymbolAddress((void**)&inv, g_inv32);
        build_inv32_kernel<<<bblocks, threads>>>(coords, mask, inv, BP, P);
        launch_pdl(cgrid, bev_write32_kernel, emb, coords, mask,
                   (const int*)inv, out, BP, P, C);
    }
}